// round 15
// baseline (speedup 1.0000x reference)
#include <cuda_runtime.h>
#include <cuda_bf16.h>
#include <cuda_fp16.h>
#include <cstdint>
#include <cstddef>

// Problem constants
#define BB 8
#define LL 2048
#define DD 256

// ---------------------------------------------------------------------------
// Scratch (__device__ globals; no allocation allowed)
// ---------------------------------------------------------------------------
__device__ __half         g_E [(size_t)BB * LL * LL];      // E fp16 (67 MB)
__device__ __half         g_xh[(size_t)BB * LL * DD];      // x hi/lo fp16 (exact split)
__device__ __half         g_xl[(size_t)BB * LL * DD];
__device__ __half         g_Wf[3][DD * DD];                // Wq,Wk,Wv fp16 (hi only)
__device__ __half         g_Qh[(size_t)BB * LL * DD];      // fp16 single operands
__device__ __half         g_Kh[(size_t)BB * LL * DD];
__device__ __half         g_VTh[(size_t)BB * DD * LL];     // V^T fp16 [b][d][l]
__device__ float g_pm[BB][16][LL];
__device__ float g_ps[BB][16][LL];
__device__ float g_m [BB][LL];
__device__ float g_is[BB][LL];

// ---------------------------------------------------------------------------
// Helpers
// ---------------------------------------------------------------------------
__device__ __forceinline__ uint32_t smem_u32(const void* p) {
    uint32_t a;
    asm("{ .reg .u64 t; cvta.to.shared.u64 t, %1; cvt.u32.u64 %0, t; }"
        : "=r"(a) : "l"(p));
    return a;
}

#define LDSM4(r, addr)                                                        \
    asm volatile("ldmatrix.sync.aligned.m8n8.x4.shared.b16 {%0,%1,%2,%3}, [%4];" \
                 : "=r"((r)[0]), "=r"((r)[1]), "=r"((r)[2]), "=r"((r)[3])     \
                 : "r"(addr))

#define MMA_F16(d, a, b0, b1)                                                 \
    asm volatile("mma.sync.aligned.m16n8k16.row.col.f32.f16.f16.f32 "         \
                 "{%0,%1,%2,%3}, {%4,%5,%6,%7}, {%8,%9}, {%0,%1,%2,%3};"      \
                 : "+f"((d)[0]), "+f"((d)[1]), "+f"((d)[2]), "+f"((d)[3])     \
                 : "r"((a)[0]), "r"((a)[1]), "r"((a)[2]), "r"((a)[3]),        \
                   "r"(b0), "r"(b1))

#define CP16(dst, src)                                                        \
    asm volatile("cp.async.cg.shared.global [%0], [%1], 16;"                  \
                 :: "r"(dst), "l"(src))
#define CP_COMMIT() asm volatile("cp.async.commit_group;" ::: "memory")
#define CP_WAIT1()  asm volatile("cp.async.wait_group 1;" ::: "memory")
#define CP_WAIT0()  asm volatile("cp.async.wait_group 0;" ::: "memory")

// Fast exp on the fma pipe (no MUFU); rel err ~2.4e-6
__device__ __forceinline__ float fexp(float x)
{
    x = fmaxf(x, -87.0f);
    float y = x * 1.4426950408889634f;
    float t = y + 12582912.0f;
    int   i = __float_as_int(t) - 0x4B400000;
    float f = y - (t - 12582912.0f);
    float p = 1.3333558146e-3f;
    p = fmaf(p, f, 9.6181291076e-3f);
    p = fmaf(p, f, 5.5504108664e-2f);
    p = fmaf(p, f, 2.4022650696e-1f);
    p = fmaf(p, f, 6.9314718056e-1f);
    p = fmaf(p, f, 1.0f);
    return __int_as_float(__float_as_int(p) + (i << 23));
}

__device__ __forceinline__ uint32_t h2pack(float a, float b)
{
    __half2 hh = __floats2half2_rn(a, b);
    return *reinterpret_cast<uint32_t*>(&hh);
}

// ---------------------------------------------------------------------------
// x: fp32 -> fp16 hi/lo exact split (float4 per thread)
// ---------------------------------------------------------------------------
__global__ __launch_bounds__(256)
void splitx_kernel(const float* __restrict__ src)
{
    const size_t i = ((size_t)blockIdx.x * 256 + threadIdx.x) * 4;
    float4 v4 = *reinterpret_cast<const float4*>(src + i);
    float v[4] = {v4.x, v4.y, v4.z, v4.w};
    __half h[4], l[4];
#pragma unroll
    for (int j = 0; j < 4; j++) {
        h[j] = __float2half(v[j]);
        l[j] = __float2half(v[j] - __half2float(h[j]));
    }
    *reinterpret_cast<uint2*>(&g_xh[i]) = make_uint2(
        (uint32_t)*(uint16_t*)&h[0] | ((uint32_t)*(uint16_t*)&h[1] << 16),
        (uint32_t)*(uint16_t*)&h[2] | ((uint32_t)*(uint16_t*)&h[3] << 16));
    *reinterpret_cast<uint2*>(&g_xl[i]) = make_uint2(
        (uint32_t)*(uint16_t*)&l[0] | ((uint32_t)*(uint16_t*)&l[1] << 16),
        (uint32_t)*(uint16_t*)&l[2] | ((uint32_t)*(uint16_t*)&l[3] << 16));
}

// W: fp32 -> fp16 (blockIdx.y selects Wq/Wk/Wv)
__global__ __launch_bounds__(256)
void cvtw_kernel(const float* __restrict__ Wq, const float* __restrict__ Wk,
                 const float* __restrict__ Wv)
{
    const int w = blockIdx.y;
    const float* src = (w == 0) ? Wq : (w == 1) ? Wk : Wv;
    const size_t i = ((size_t)blockIdx.x * 256 + threadIdx.x) * 4;
    float4 v4 = *reinterpret_cast<const float4*>(src + i);
    *reinterpret_cast<uint2*>(&g_Wf[w][i]) = make_uint2(
        h2pack(v4.x, v4.y), h2pack(v4.z, v4.w));
}

// ---------------------------------------------------------------------------
// MMA kernels. PITCH=80 smem rows; cp.async 3-stage pipeline.
// ---------------------------------------------------------------------------
#define PITCH 80
#define TILEB  (128 * PITCH)           // 10240
#define TILEB2 (256 * PITCH)           // 20480
#define BUF2  (2 * TILEB)              // mm_e stage: Ah|Bh
#define BUF3  (3 * TILEB)              // mm_qkv stage: Ah|Al|Bh
#define SMEM_E  (3 * BUF2)             // 61440
#define SMEM_Q  (3 * BUF3)             // 92160
#define SMEM_AV (2 * TILEB + 3 * TILEB2)  // 81920: A x2 | B(256) x3

#define CPSTAGE2(dh, dl, srch, srcl, ld, kc)                                  \
    _Pragma("unroll")                                                         \
    for (int t = 0; t < 2; t++) {                                             \
        const int q = tid + t * 256;                                          \
        const int row = q >> 2, seg = q & 3;                                  \
        const uint32_t so = row * PITCH + seg * 16;                           \
        const size_t go = (size_t)row * (ld) + (size_t)(kc) * 32 + seg * 8;   \
        CP16((dh) + so, (srch) + go);                                         \
        CP16((dl) + so, (srcl) + go);                                         \
    }

#define CPSTAGE1(dh, srch, ld, kc)                                            \
    _Pragma("unroll")                                                         \
    for (int t = 0; t < 2; t++) {                                             \
        const int q = tid + t * 256;                                          \
        const int row = q >> 2, seg = q & 3;                                  \
        const uint32_t so = row * PITCH + seg * 16;                           \
        const size_t go = (size_t)row * (ld) + (size_t)(kc) * 32 + seg * 8;   \
        CP16((dh) + so, (srch) + go);                                         \
    }

// 256-row B tile staged by 512 threads
#define CPSTAGE1W(dh, srch, ld, kc)                                           \
    _Pragma("unroll")                                                         \
    for (int t = 0; t < 2; t++) {                                             \
        const int q = tid + t * 512;                                          \
        const int row = q >> 2, seg = q & 3;                                  \
        const uint32_t so = row * PITCH + seg * 16;                           \
        const size_t go = (size_t)row * (ld) + (size_t)(kc) * 32 + seg * 8;   \
        CP16((dh) + so, (srch) + go);                                         \
    }

// 1-term fp16: D += Ah*Bh (warp tile 64x32; uses relA/relB)
#define COMPUTE1(aH, bH)                                                      \
    _Pragma("unroll")                                                         \
    for (int kk = 0; kk < 2; kk++) {                                          \
        uint32_t bhf[2][4];                                                   \
        LDSM4(bhf[0], (bH) + relB + kk * 32);                                 \
        LDSM4(bhf[1], (bH) + relB + 16 * PITCH + kk * 32);                    \
        _Pragma("unroll")                                                     \
        for (int mt = 0; mt < 4; mt++) {                                      \
            uint32_t ah[4];                                                   \
            LDSM4(ah, (aH) + relA + mt * 16 * PITCH + kk * 32);               \
            _Pragma("unroll")                                                 \
            for (int g = 0; g < 2; g++) {                                     \
                _Pragma("unroll")                                             \
                for (int h = 0; h < 2; h++) {                                 \
                    float* acc = d[mt * 4 + g * 2 + h];                       \
                    MMA_F16(acc, ah, bhf[g][h], bhf[g][h + 2]);               \
                }                                                             \
            }                                                                 \
        }                                                                     \
    }

// 2-term fp16: D += Ah*Bh + Al*Bh
#define COMPUTE2(aH, aL, bH)                                                  \
    _Pragma("unroll")                                                         \
    for (int kk = 0; kk < 2; kk++) {                                          \
        uint32_t bhf[2][4];                                                   \
        LDSM4(bhf[0], (bH) + relB + kk * 32);                                 \
        LDSM4(bhf[1], (bH) + relB + 16 * PITCH + kk * 32);                    \
        _Pragma("unroll")                                                     \
        for (int mt = 0; mt < 4; mt++) {                                      \
            uint32_t ah[4], al[4];                                            \
            LDSM4(ah, (aH) + relA + mt * 16 * PITCH + kk * 32);               \
            LDSM4(al, (aL) + relA + mt * 16 * PITCH + kk * 32);               \
            _Pragma("unroll")                                                 \
            for (int g = 0; g < 2; g++) {                                     \
                _Pragma("unroll")                                             \
                for (int h = 0; h < 2; h++) {                                 \
                    float* acc = d[mt * 4 + g * 2 + h];                       \
                    MMA_F16(acc, ah, bhf[g][h], bhf[g][h + 2]);               \
                    MMA_F16(acc, al, bhf[g][h], bhf[g][h + 2]);               \
                }                                                             \
            }                                                                 \
        }                                                                     \
    }

#define MM_PROLOGUE()                                                         \
    extern __shared__ __align__(16) uint8_t smem[];                           \
    const uint32_t sb = smem_u32(smem);                                       \
    const int tid = threadIdx.x;                                              \
    const int lane = tid & 31;                                                \
    const int wm = (tid >> 5) & 1;                                            \
    const int wn = tid >> 6;                                                  \
    const uint32_t lrow = lane & 15, lhalf = lane >> 4;                       \
    const uint32_t relA = (wm * 64 + lrow) * PITCH + lhalf * 16;              \
    const uint32_t relB = (wn * 32 + lrow) * PITCH + lhalf * 16;              \
    float d[16][4];                                                           \
    _Pragma("unroll")                                                         \
    for (int i = 0; i < 16; i++)                                              \
        _Pragma("unroll")                                                     \
        for (int j = 0; j < 4; j++) d[i][j] = 0.0f;

// mm_e: 3 stages of [Ah|Bh]
#define BE_AH(s) (sb + (s) * BUF2)
#define BE_BH(s) (sb + (s) * BUF2 + TILEB)
// mm_qkv: 3 stages of [Ah|Al|Bh]
#define BQ_AH(s) (sb + (s) * BUF3)
#define BQ_AL(s) (sb + (s) * BUF3 + TILEB)
#define BQ_BH(s) (sb + (s) * BUF3 + 2 * TILEB)
// mm_av: A x2 (128-row), B x3 (256-row)
#define BA_A(s)  (sb + (s) * TILEB)
#define BA_B(s)  (sb + 2 * TILEB + (s) * TILEB2)

// ---------------------------------------------------------------------------
// E = Q K^T / 16 (fp16 1-term), E stored fp16, fused softmax partials (fp32).
// ---------------------------------------------------------------------------
__global__ __launch_bounds__(256, 2)
void mm_e(__half* __restrict__ Eh)
{
    MM_PROLOGUE();
    const int b = blockIdx.z;
    const int n0 = blockIdx.x * 128, m0 = blockIdx.y * 128;

    const __half* pAh = g_Qh + (size_t)b * LL * DD + (size_t)m0 * DD;
    const __half* pBh = g_Kh + (size_t)b * LL * DD + (size_t)n0 * DD;

    const int NCH = DD / 32;   // 8
    CPSTAGE1(BE_AH(0), pAh, DD, 0);
    CPSTAGE1(BE_BH(0), pBh, DD, 0);
    CP_COMMIT();
    CPSTAGE1(BE_AH(1), pAh, DD, 1);
    CPSTAGE1(BE_BH(1), pBh, DD, 1);
    CP_COMMIT();

    int bi = 0;
    for (int kc = 0; kc < NCH; kc++) {
        if (kc == NCH - 1) { CP_WAIT0(); } else { CP_WAIT1(); }
        __syncthreads();
        COMPUTE1(BE_AH(bi), BE_BH(bi));
        if (kc + 2 < NCH) {
            const int s = (bi + 2 >= 3) ? bi - 1 : bi + 2;
            CPSTAGE1(BE_AH(s), pAh, DD, kc + 2);
            CPSTAGE1(BE_BH(s), pBh, DD, kc + 2);
            CP_COMMIT();
        }
        bi = (bi + 1 == 3) ? 0 : bi + 1;
    }

#pragma unroll
    for (int i = 0; i < 16; i++)
#pragma unroll
        for (int j = 0; j < 4; j++) d[i][j] *= (1.0f / 16.0f);

    __half* Cb = Eh + (size_t)b * LL * LL;
#pragma unroll
    for (int mt = 0; mt < 4; mt++) {
#pragma unroll
        for (int ni = 0; ni < 4; ni++) {
            const float* acc = d[mt * 4 + ni];
            const int row = m0 + wm * 64 + mt * 16 + (lane >> 2);
            const int col = n0 + wn * 32 + ni * 8 + (lane & 3) * 2;
            *reinterpret_cast<uint32_t*>(&Cb[(size_t)row * LL + col]) =
                h2pack(acc[0], acc[1]);
            *reinterpret_cast<uint32_t*>(&Cb[(size_t)(row + 8) * LL + col]) =
                h2pack(acc[2], acc[3]);
        }
    }

    float* sMx = reinterpret_cast<float*>(smem);
    float* sSm = reinterpret_cast<float*>(smem) + 256;
    __syncthreads();
#pragma unroll
    for (int ni = 0; ni < 4; ni++) {
#pragma unroll
        for (int p = 0; p < 2; p++) {
            float mx = -1e30f;
#pragma unroll
            for (int mt = 0; mt < 4; mt++)
                mx = fmaxf(mx, fmaxf(d[mt * 4 + ni][p], d[mt * 4 + ni][p + 2]));
#pragma unroll
            for (int off = 4; off < 32; off <<= 1)
                mx = fmaxf(mx, __shfl_xor_sync(0xFFFFFFFFu, mx, off));
            float sm = 0.0f;
#pragma unroll
            for (int mt = 0; mt < 4; mt++)
                sm += fexp(d[mt * 4 + ni][p] - mx) + fexp(d[mt * 4 + ni][p + 2] - mx);
#pragma unroll
            for (int off = 4; off < 32; off <<= 1)
                sm += __shfl_xor_sync(0xFFFFFFFFu, sm, off);
            if ((lane >> 2) == 0) {
                const int c = wn * 32 + ni * 8 + (lane & 3) * 2 + p;
                sMx[wm * 128 + c] = mx;
                sSm[wm * 128 + c] = sm;
            }
        }
    }
    __syncthreads();
    if (tid < 128) {
        float m0v = sMx[tid], m1v = sMx[128 + tid];
        float nm = fmaxf(m0v, m1v);
        float s = sSm[tid] * fexp(m0v - nm) + sSm[128 + tid] * fexp(m1v - nm);
        g_pm[b][blockIdx.y][n0 + tid] = nm;
        g_ps[b][blockIdx.y][n0 + tid] = s;
    }
}

// ---------------------------------------------------------------------------
// C = A V^T (fp16 1-term), N=256 single pass, 512 threads (16 warps 2m x 8n).
// E read ONCE, exp transform ONCE, A written unconditionally.
// 3-stage B pipeline, 2-stage A (transform after compute).
// ---------------------------------------------------------------------------
__global__ __launch_bounds__(512, 1)
void mm_av(const __half* __restrict__ Eh, float* __restrict__ Aout,
           float* __restrict__ Cout)
{
    extern __shared__ __align__(16) uint8_t smem[];
    const uint32_t sb = smem_u32(smem);
    const int tid = threadIdx.x;
    const int lane = tid & 31;
    const int wm = (tid >> 5) & 1;       // 2 m-groups of 64 rows
    const int wn = tid >> 6;             // 8 n-groups of 32 cols
    const uint32_t lrow = lane & 15, lhalf = lane >> 4;
    const uint32_t relA = (wm * 64 + lrow) * PITCH + lhalf * 16;
    const uint32_t relB = (wn * 32 + lrow) * PITCH + lhalf * 16;
    float d[16][4];
#pragma unroll
    for (int i = 0; i < 16; i++)
#pragma unroll
        for (int j = 0; j < 4; j++) d[i][j] = 0.0f;

    const int b = blockIdx.z;
    const int m0 = blockIdx.y * 128;

    const __half* pE  = Eh + (size_t)b * LL * LL + (size_t)m0 * LL;
    float*        pA  = Aout + (size_t)b * LL * LL + (size_t)m0 * LL;
    const __half* pBh = g_VTh + (size_t)b * DD * LL;    // full 256 d-rows

    const int NCH = LL / 32;   // 64

    uint2 e2[2];
#pragma unroll
    for (int t = 0; t < 2; t++) {
        const int q = tid + t * 512;
        const int row = q >> 3, seg = q & 7;
        e2[t] = *reinterpret_cast<const uint2*>(pE + (size_t)row * LL + seg * 4);
    }
    CPSTAGE1W(BA_B(0), pBh, LL, 0);
    CP_COMMIT();
    CPSTAGE1W(BA_B(1), pBh, LL, 1);
    CP_COMMIT();

    // transform chunk 0 into A buf 0; prefetch E chunk 1
    {
#pragma unroll
        for (int t = 0; t < 2; t++) {
            const int q = tid + t * 512;
            const int row = q >> 3, seg = q & 7;
            const int k = seg * 4;
            float2 f0 = __half22float2(*reinterpret_cast<__half2*>(&e2[t].x));
            float2 f1 = __half22float2(*reinterpret_cast<__half2*>(&e2[t].y));
            float4 m4 = *reinterpret_cast<const float4*>(&g_m[b][k]);
            float4 i4 = *reinterpret_cast<const float4*>(&g_is[b][k]);
            float v[4];
            v[0] = fexp(f0.x - m4.x) * i4.x;
            v[1] = fexp(f0.y - m4.y) * i4.y;
            v[2] = fexp(f1.x - m4.z) * i4.z;
            v[3] = fexp(f1.y - m4.w) * i4.w;
            *reinterpret_cast<float4*>(pA + (size_t)row * LL + k) =
                make_float4(v[0], v[1], v[2], v[3]);
            const uint32_t so = row * PITCH + seg * 8;
            *reinterpret_cast<uint2*>(smem + so) =
                make_uint2(h2pack(v[0], v[1]), h2pack(v[2], v[3]));
        }
#pragma unroll
        for (int t = 0; t < 2; t++) {
            const int q = tid + t * 512;
            const int row = q >> 3, seg = q & 7;
            e2[t] = *reinterpret_cast<const uint2*>(pE + (size_t)row * LL + 32 + seg * 4);
        }
    }

    int abuf = 0, bbuf = 0;
    for (int kc = 0; kc < NCH; kc++) {
        if (kc == NCH - 1) { CP_WAIT0(); } else { CP_WAIT1(); }
        __syncthreads();
        COMPUTE1(BA_A(abuf), BA_B(bbuf));
        if (kc + 1 < NCH) {
            const int c = kc + 1;
            const int na = abuf ^ 1;
#pragma unroll
            for (int t = 0; t < 2; t++) {
                const int q = tid + t * 512;
                const int row = q >> 3, seg = q & 7;
                const int k = c * 32 + seg * 4;
                float2 f0 = __half22float2(*reinterpret_cast<__half2*>(&e2[t].x));
                float2 f1 = __half22float2(*reinterpret_cast<__half2*>(&e2[t].y));
                float4 m4 = *reinterpret_cast<const float4*>(&g_m[b][k]);
                float4 i4 = *reinterpret_cast<const float4*>(&g_is[b][k]);
                float v[4];
                v[0] = fexp(f0.x - m4.x) * i4.x;
                v[1] = fexp(f0.y - m4.y) * i4.y;
                v[2] = fexp(f1.x - m4.z) * i4.z;
                v[3] = fexp(f1.y - m4.w) * i4.w;
                *reinterpret_cast<float4*>(pA + (size_t)row * LL + k) =
                    make_float4(v[0], v[1], v[2], v[3]);
                const uint32_t so = row * PITCH + seg * 8;
                *reinterpret_cast<uint2*>(smem + na * TILEB + so) =
                    make_uint2(h2pack(v[0], v[1]), h2pack(v[2], v[3]));
            }
            if (c + 1 < NCH) {
#pragma unroll
                for (int t = 0; t < 2; t++) {
                    const int q = tid + t * 512;
                    const int row = q >> 3, seg = q & 7;
                    e2[t] = *reinterpret_cast<const uint2*>(
                        pE + (size_t)row * LL + (size_t)(c + 1) * 32 + seg * 4);
                }
            }
        }
        if (kc + 2 < NCH) {
            const int s = (bbuf + 2 >= 3) ? bbuf - 1 : bbuf + 2;
            CPSTAGE1W(BA_B(s), pBh, LL, kc + 2);
            CP_COMMIT();
        }
        abuf ^= 1;
        bbuf = (bbuf + 1 == 3) ? 0 : bbuf + 1;
    }

    float* Cb = Cout + (size_t)b * 2 * LL * DD;
#pragma unroll
    for (int mt = 0; mt < 4; mt++) {
#pragma unroll
        for (int ni = 0; ni < 4; ni++) {
            const float* acc = d[mt * 4 + ni];
            const int row = m0 + wm * 64 + mt * 16 + (lane >> 2);
            const int col = wn * 32 + ni * 8 + (lane & 3) * 2;
            *reinterpret_cast<float2*>(&Cb[(size_t)row * DD + col]) =
                make_float2(acc[0], acc[1]);
            *reinterpret_cast<float2*>(&Cb[(size_t)(row + 8) * DD + col]) =
                make_float2(acc[2], acc[3]);
        }
    }
}

// ---------------------------------------------------------------------------
// QKV (fp16 2-term): {Q,K,V}[r,n] = x[r,:].W[n,:] + b[n]
// w==2 (V): transposed fp16 output written directly via smem transpose.
// ---------------------------------------------------------------------------
__global__ __launch_bounds__(256, 2)
void mm_qkv(const float* __restrict__ bq, const float* __restrict__ bk,
            const float* __restrict__ bv, float* __restrict__ Sp)
{
    MM_PROLOGUE();
    const int w = blockIdx.z;
    const int n0 = blockIdx.x * 128, m0 = blockIdx.y * 128;

    const __half* pAh = g_xh + (size_t)m0 * DD;
    const __half* pAl = g_xl + (size_t)m0 * DD;
    const __half* pBh = g_Wf[w] + (size_t)n0 * DD;

    const int NCH = DD / 32;
    CPSTAGE2(BQ_AH(0), BQ_AL(0), pAh, pAl, DD, 0);
    CPSTAGE1(BQ_BH(0), pBh, DD, 0);
    CP_COMMIT();
    CPSTAGE2(BQ_AH(1), BQ_AL(1), pAh, pAl, DD, 1);
    CPSTAGE1(BQ_BH(1), pBh, DD, 1);
    CP_COMMIT();

    int bi = 0;
    for (int kc = 0; kc < NCH; kc++) {
        if (kc == NCH - 1) { CP_WAIT0(); } else { CP_WAIT1(); }
        __syncthreads();
        COMPUTE2(BQ_AH(bi), BQ_AL(bi), BQ_BH(bi));
        if (kc + 2 < NCH) {
            const int s = (bi + 2 >= 3) ? bi - 1 : bi + 2;
            CPSTAGE2(BQ_AH(s), BQ_AL(s), pAh, pAl, DD, kc + 2);
            CPSTAGE1(BQ_BH(s), pBh, DD, kc + 2);
            CP_COMMIT();
        }
        bi = (bi + 1 == 3) ? 0 : bi + 1;
    }

    const float* bias = (w == 0) ? bq : (w == 1) ? bk : bv;
    const int b = m0 >> 11;            // batch (m-tiles never straddle batches)
    const int l0 = m0 & 2047;

    if (w < 2) {
#pragma unroll
        for (int mt = 0; mt < 4; mt++) {
#pragma unroll
            for (int ni = 0; ni < 4; ni++) {
                float* acc = d[mt * 4 + ni];
                const int row = m0 + wm * 64 + mt * 16 + (lane >> 2);
                const int col = n0 + wn * 32 + ni * 8 + (lane & 3) * 2;
                const float b0 = bias[col], b1 = bias[col + 1];
                float v0 = acc[0] + b0, v1 = acc[1] + b1;
                float v2 = acc[2] + b0, v3 = acc[3] + b1;
                const size_t o0 = (size_t)row * DD + col;
                const size_t o1 = (size_t)(row + 8) * DD + col;
                if (w == 0) {
                    const int li = row & 2047, li8 = (row + 8) & 2047;
                    float* q0 = Sp + (size_t)b * 2 * LL * DD + (size_t)li * DD + col;
                    float* q1 = Sp + (size_t)b * 2 * LL * DD + (size_t)li8 * DD + col;
                    *reinterpret_cast<float2*>(q0) = make_float2(v0, v1);
                    *reinterpret_cast<float2*>(q1) = make_float2(v2, v3);
                    *reinterpret_cast<uint32_t*>(&g_Qh[o0]) = h2pack(v0, v1);
                    *reinterpret_cast<uint32_t*>(&g_Qh[o1]) = h2pack(v2, v3);
                } else {
                    *reinterpret_cast<uint32_t*>(&g_Kh[o0]) = h2pack(v0, v1);
                    *reinterpret_cast<uint32_t*>(&g_Kh[o1]) = h2pack(v2, v3);
                }
            }
        }
    } else {
        // V: transpose 128(l) x 128(d) tile in smem -> g_VTh[b][d][l] fp16
        __syncthreads();
        __half* sT = reinterpret_cast<__half*>(smem);  // [128 d][pitch 136]
#pragma unroll
        for (int mt = 0; mt < 4; mt++) {
#pragma unroll
            for (int ni = 0; ni < 4; ni++) {
                const float* acc = d[mt * 4 + ni];
                const int lr = wm * 64 + mt * 16 + (lane >> 2);       // local l
                const int dc = wn * 32 + ni * 8 + (lane & 3) * 2;     // local d
                const float b0 = bias[n0 + dc], b1 = bias[n0 + dc + 1];
                sT[(dc    ) * 136 + lr    ] = __float2half(acc[0] + b0);
                sT[(dc + 1) * 136 + lr    ] = __float2half(acc[1] + b1);
                sT[(dc    ) * 136 + lr + 8] = __float2half(acc[2] + b0);
                sT[(dc + 1) * 136 + lr + 8] = __float2half(acc[3] + b1);
            }
        }
        __syncthreads();
        __half* Tb = g_VTh + (size_t)b * DD * LL;
#pragma unroll
        for (int t = 0; t < 8; t++) {
            const int i = tid + t * 256;       // 0..2047
            const int dr = i >> 4, seg = i & 15;
            *reinterpret_cast<uint4*>(&Tb[(size_t)(n0 + dr) * LL + l0 + seg * 8]) =
                *reinterpret_cast<const uint4*>(&sT[dr * 136 + seg * 8]);
        }
    }
}

// ---------------------------------------------------------------------------
// Softmax combine (16 partials per column)
// ---------------------------------------------------------------------------
__global__ __launch_bounds__(256)
void softmax_combine()
{
    const int b = blockIdx.y;
    const int col = blockIdx.x * 256 + threadIdx.x;
    float m = -1e30f;
#pragma unroll
    for (int c = 0; c < 16; c++) m = fmaxf(m, g_pm[b][c][col]);
    float s = 0.f;
#pragma unroll
    for (int c = 0; c < 16; c++) s += g_ps[b][c][col] * fexp(g_pm[b][c][col] - m);
    g_m[b][col] = m;
    g_is[b][col] = 1.0f / s;
}

// ---------------------------------------------------------------------------
// Launch
// ---------------------------------------------------------------------------
extern "C" void kernel_launch(void* const* d_in, const int* in_sizes, int n_in,
                              void* d_out, int out_size)
{
    const float* x  = (const float*)d_in[0];
    const float* Wq = (const float*)d_in[1];
    const float* bq = (const float*)d_in[2];
    const float* Wk = (const float*)d_in[3];
    const float* bk = (const float*)d_in[4];
    const float* Wv = (const float*)d_in[5];
    const float* bv = (const float*)d_in[6];

    float* out  = (float*)d_out;
    float* Sp   = out;                                  // [B, 2L, D]
    float* Aout = out + (size_t)BB * 2 * LL * DD;       // [B, L, L]

    __half *gE;
    cudaGetSymbolAddress((void**)&gE, g_E);

    cudaFuncSetAttribute(mm_e,   cudaFuncAttributeMaxDynamicSharedMemorySize, SMEM_E);
    cudaFuncSetAttribute(mm_av,  cudaFuncAttributeMaxDynamicSharedMemorySize, SMEM_AV);
    cudaFuncSetAttribute(mm_qkv, cudaFuncAttributeMaxDynamicSharedMemorySize, SMEM_Q);

    // 1) split x (fp16 hi/lo) and convert W (fp16)
    const size_t nx = (size_t)BB * LL * DD;
    splitx_kernel<<<(unsigned)(nx / 1024), 256>>>(x);
    cvtw_kernel<<<dim3(DD * DD / 1024, 3), 256>>>(Wq, Wk, Wv);

    // 2) QKV on tensor cores (fp16 2-term); V written transposed fp16
    mm_qkv<<<dim3(2, (BB * LL) / 128, 3), 256, SMEM_Q>>>(bq, bk, bv, Sp);

    // 3) E = Q K^T / 16 (fp16 1-term), E stored fp16, fused softmax partials
    mm_e<<<dim3(LL / 128, LL / 128, BB), 256, SMEM_E>>>(gE);

    // 4) softmax finalize
    softmax_combine<<<dim3(LL / 256, BB), 256>>>();

    // 5) C = A V (N=256 single pass, 512 threads; E read once, exp once)
    mm_av<<<dim3(1, LL / 128, BB), 512, SMEM_AV>>>(gE, Aout, Sp + (size_t)LL * DD);

    (void)in_sizes; (void)n_in; (void)out_size;
}

// round 16
// speedup vs baseline: 1.1218x; 1.1218x over previous
#include <cuda_runtime.h>
#include <cuda_bf16.h>
#include <cuda_fp16.h>
#include <cstdint>
#include <cstddef>

// Problem constants
#define BB 8
#define LL 2048
#define DD 256

// ---------------------------------------------------------------------------
// Scratch (__device__ globals; no allocation allowed)
// ---------------------------------------------------------------------------
__device__ __half         g_E [(size_t)BB * LL * LL];      // E fp16 (67 MB)
__device__ __half         g_xf[(size_t)BB * LL * DD];      // x fp16
__device__ __half         g_Wf[3][DD * DD];                // Wq,Wk,Wv fp16
__device__ __half         g_Qh[(size_t)BB * LL * DD];      // fp16 single operands
__device__ __half         g_Kh[(size_t)BB * LL * DD];
__device__ __half         g_VTh[(size_t)BB * DD * LL];     // V^T fp16 [b][d][l]
__device__ float g_pm[BB][16][LL];
__device__ float g_ps[BB][16][LL];
__device__ float g_m [BB][LL];
__device__ float g_is[BB][LL];

// ---------------------------------------------------------------------------
// Helpers
// ---------------------------------------------------------------------------
__device__ __forceinline__ uint32_t smem_u32(const void* p) {
    uint32_t a;
    asm("{ .reg .u64 t; cvta.to.shared.u64 t, %1; cvt.u32.u64 %0, t; }"
        : "=r"(a) : "l"(p));
    return a;
}

#define LDSM4(r, addr)                                                        \
    asm volatile("ldmatrix.sync.aligned.m8n8.x4.shared.b16 {%0,%1,%2,%3}, [%4];" \
                 : "=r"((r)[0]), "=r"((r)[1]), "=r"((r)[2]), "=r"((r)[3])     \
                 : "r"(addr))

#define MMA_F16(d, a, b0, b1)                                                 \
    asm volatile("mma.sync.aligned.m16n8k16.row.col.f32.f16.f16.f32 "         \
                 "{%0,%1,%2,%3}, {%4,%5,%6,%7}, {%8,%9}, {%0,%1,%2,%3};"      \
                 : "+f"((d)[0]), "+f"((d)[1]), "+f"((d)[2]), "+f"((d)[3])     \
                 : "r"((a)[0]), "r"((a)[1]), "r"((a)[2]), "r"((a)[3]),        \
                   "r"(b0), "r"(b1))

#define CP16(dst, src)                                                        \
    asm volatile("cp.async.cg.shared.global [%0], [%1], 16;"                  \
                 :: "r"(dst), "l"(src))
#define CP_COMMIT() asm volatile("cp.async.commit_group;" ::: "memory")
#define CP_WAIT1()  asm volatile("cp.async.wait_group 1;" ::: "memory")
#define CP_WAIT0()  asm volatile("cp.async.wait_group 0;" ::: "memory")

// Fast exp on the fma pipe (no MUFU); rel err ~2.4e-6
__device__ __forceinline__ float fexp(float x)
{
    x = fmaxf(x, -87.0f);
    float y = x * 1.4426950408889634f;
    float t = y + 12582912.0f;
    int   i = __float_as_int(t) - 0x4B400000;
    float f = y - (t - 12582912.0f);
    float p = 1.3333558146e-3f;
    p = fmaf(p, f, 9.6181291076e-3f);
    p = fmaf(p, f, 5.5504108664e-2f);
    p = fmaf(p, f, 2.4022650696e-1f);
    p = fmaf(p, f, 6.9314718056e-1f);
    p = fmaf(p, f, 1.0f);
    return __int_as_float(__float_as_int(p) + (i << 23));
}

__device__ __forceinline__ uint32_t h2pack(float a, float b)
{
    __half2 hh = __floats2half2_rn(a, b);
    return *reinterpret_cast<uint32_t*>(&hh);
}

// ---------------------------------------------------------------------------
// x: fp32 -> fp16
// ---------------------------------------------------------------------------
__global__ __launch_bounds__(256)
void cvtx_kernel(const float* __restrict__ src)
{
    const size_t i = ((size_t)blockIdx.x * 256 + threadIdx.x) * 4;
    float4 v4 = *reinterpret_cast<const float4*>(src + i);
    *reinterpret_cast<uint2*>(&g_xf[i]) = make_uint2(
        h2pack(v4.x, v4.y), h2pack(v4.z, v4.w));
}

// W: fp32 -> fp16 (blockIdx.y selects Wq/Wk/Wv)
__global__ __launch_bounds__(256)
void cvtw_kernel(const float* __restrict__ Wq, const float* __restrict__ Wk,
                 const float* __restrict__ Wv)
{
    const int w = blockIdx.y;
    const float* src = (w == 0) ? Wq : (w == 1) ? Wk : Wv;
    const size_t i = ((size_t)blockIdx.x * 256 + threadIdx.x) * 4;
    float4 v4 = *reinterpret_cast<const float4*>(src + i);
    *reinterpret_cast<uint2*>(&g_Wf[w][i]) = make_uint2(
        h2pack(v4.x, v4.y), h2pack(v4.z, v4.w));
}

// ---------------------------------------------------------------------------
// MMA kernels: CTA tile 128x128, BK=32, 256 threads (8 warps 64x32).
// PITCH=80 smem rows; cp.async 3-stage pipeline, ONE barrier per chunk.
// ---------------------------------------------------------------------------
#define PITCH 80
#define TILEB (128 * PITCH)            // 10240
#define BUF2  (2 * TILEB)              // [Ah|Bh] per stage
#define SMEM_E  (3 * BUF2)             // 61440 (also mm_qkv)
#define SMEM_AV (5 * TILEB)            // 51200: A x2 | B x3

#define CPSTAGE1(dh, srch, ld, kc)                                            \
    _Pragma("unroll")                                                         \
    for (int t = 0; t < 2; t++) {                                             \
        const int q = tid + t * 256;                                          \
        const int row = q >> 2, seg = q & 3;                                  \
        const uint32_t so = row * PITCH + seg * 16;                           \
        const size_t go = (size_t)row * (ld) + (size_t)(kc) * 32 + seg * 8;   \
        CP16((dh) + so, (srch) + go);                                         \
    }

// 1-term fp16: D += Ah*Bh
#define COMPUTE1(aH, bH)                                                      \
    _Pragma("unroll")                                                         \
    for (int kk = 0; kk < 2; kk++) {                                          \
        uint32_t bhf[2][4];                                                   \
        LDSM4(bhf[0], (bH) + relB + kk * 32);                                 \
        LDSM4(bhf[1], (bH) + relB + 16 * PITCH + kk * 32);                    \
        _Pragma("unroll")                                                     \
        for (int mt = 0; mt < 4; mt++) {                                      \
            uint32_t ah[4];                                                   \
            LDSM4(ah, (aH) + relA + mt * 16 * PITCH + kk * 32);               \
            _Pragma("unroll")                                                 \
            for (int g = 0; g < 2; g++) {                                     \
                _Pragma("unroll")                                             \
                for (int h = 0; h < 2; h++) {                                 \
                    float* acc = d[mt * 4 + g * 2 + h];                       \
                    MMA_F16(acc, ah, bhf[g][h], bhf[g][h + 2]);               \
                }                                                             \
            }                                                                 \
        }                                                                     \
    }

#define MM_PROLOGUE()                                                         \
    extern __shared__ __align__(16) uint8_t smem[];                           \
    const uint32_t sb = smem_u32(smem);                                       \
    const int tid = threadIdx.x;                                              \
    const int lane = tid & 31;                                                \
    const int wm = (tid >> 5) & 1;                                            \
    const int wn = tid >> 6;                                                  \
    const uint32_t lrow = lane & 15, lhalf = lane >> 4;                       \
    const uint32_t relA = (wm * 64 + lrow) * PITCH + lhalf * 16;              \
    const uint32_t relB = (wn * 32 + lrow) * PITCH + lhalf * 16;              \
    float d[16][4];                                                           \
    _Pragma("unroll")                                                         \
    for (int i = 0; i < 16; i++)                                              \
        _Pragma("unroll")                                                     \
        for (int j = 0; j < 4; j++) d[i][j] = 0.0f;

// 3-stage [Ah|Bh] buffers (mm_e, mm_qkv)
#define BE_AH(s) (sb + (s) * BUF2)
#define BE_BH(s) (sb + (s) * BUF2 + TILEB)
// mm_av: A x2, B x3
#define BA_A(s)  (sb + (s) * TILEB)
#define BA_B(s)  (sb + (2 + (s)) * TILEB)

// ---------------------------------------------------------------------------
// E = Q K^T / 16 (fp16 1-term), E stored fp16, fused softmax partials (fp32).
// Max-first reduction in the epilogue.
// ---------------------------------------------------------------------------
__global__ __launch_bounds__(256, 2)
void mm_e(__half* __restrict__ Eh)
{
    MM_PROLOGUE();
    const int b = blockIdx.z;
    const int n0 = blockIdx.x * 128, m0 = blockIdx.y * 128;

    const __half* pAh = g_Qh + (size_t)b * LL * DD + (size_t)m0 * DD;
    const __half* pBh = g_Kh + (size_t)b * LL * DD + (size_t)n0 * DD;

    const int NCH = DD / 32;   // 8
    CPSTAGE1(BE_AH(0), pAh, DD, 0);
    CPSTAGE1(BE_BH(0), pBh, DD, 0);
    CP_COMMIT();
    CPSTAGE1(BE_AH(1), pAh, DD, 1);
    CPSTAGE1(BE_BH(1), pBh, DD, 1);
    CP_COMMIT();

    int bi = 0;
    for (int kc = 0; kc < NCH; kc++) {
        if (kc == NCH - 1) { CP_WAIT0(); } else { CP_WAIT1(); }
        __syncthreads();
        COMPUTE1(BE_AH(bi), BE_BH(bi));
        if (kc + 2 < NCH) {
            const int s = (bi + 2 >= 3) ? bi - 1 : bi + 2;
            CPSTAGE1(BE_AH(s), pAh, DD, kc + 2);
            CPSTAGE1(BE_BH(s), pBh, DD, kc + 2);
            CP_COMMIT();
        }
        bi = (bi + 1 == 3) ? 0 : bi + 1;
    }

#pragma unroll
    for (int i = 0; i < 16; i++)
#pragma unroll
        for (int j = 0; j < 4; j++) d[i][j] *= (1.0f / 16.0f);

    __half* Cb = Eh + (size_t)b * LL * LL;
#pragma unroll
    for (int mt = 0; mt < 4; mt++) {
#pragma unroll
        for (int ni = 0; ni < 4; ni++) {
            const float* acc = d[mt * 4 + ni];
            const int row = m0 + wm * 64 + mt * 16 + (lane >> 2);
            const int col = n0 + wn * 32 + ni * 8 + (lane & 3) * 2;
            *reinterpret_cast<uint32_t*>(&Cb[(size_t)row * LL + col]) =
                h2pack(acc[0], acc[1]);
            *reinterpret_cast<uint32_t*>(&Cb[(size_t)(row + 8) * LL + col]) =
                h2pack(acc[2], acc[3]);
        }
    }

    float* sMx = reinterpret_cast<float*>(smem);
    float* sSm = reinterpret_cast<float*>(smem) + 256;
    __syncthreads();
#pragma unroll
    for (int ni = 0; ni < 4; ni++) {
#pragma unroll
        for (int p = 0; p < 2; p++) {
            float mx = -1e30f;
#pragma unroll
            for (int mt = 0; mt < 4; mt++)
                mx = fmaxf(mx, fmaxf(d[mt * 4 + ni][p], d[mt * 4 + ni][p + 2]));
#pragma unroll
            for (int off = 4; off < 32; off <<= 1)
                mx = fmaxf(mx, __shfl_xor_sync(0xFFFFFFFFu, mx, off));
            float sm = 0.0f;
#pragma unroll
            for (int mt = 0; mt < 4; mt++)
                sm += fexp(d[mt * 4 + ni][p] - mx) + fexp(d[mt * 4 + ni][p + 2] - mx);
#pragma unroll
            for (int off = 4; off < 32; off <<= 1)
                sm += __shfl_xor_sync(0xFFFFFFFFu, sm, off);
            if ((lane >> 2) == 0) {
                const int c = wn * 32 + ni * 8 + (lane & 3) * 2 + p;
                sMx[wm * 128 + c] = mx;
                sSm[wm * 128 + c] = sm;
            }
        }
    }
    __syncthreads();
    if (tid < 128) {
        float m0v = sMx[tid], m1v = sMx[128 + tid];
        float nm = fmaxf(m0v, m1v);
        float s = sSm[tid] * fexp(m0v - nm) + sSm[128 + tid] * fexp(m1v - nm);
        g_pm[b][blockIdx.y][n0 + tid] = nm;
        g_ps[b][blockIdx.y][n0 + tid] = s;
    }
}

// ---------------------------------------------------------------------------
// C = A V^T (fp16 1-term), 3-stage B / 2-stage A, one barrier per chunk.
// A = exp(E_h - m[k])*is[k] transformed AFTER compute (overlaps other warps).
// n-tile x writes A fp32 for k-chunks [x*32, x*32+32).  (R14 version)
// ---------------------------------------------------------------------------
__global__ __launch_bounds__(256, 2)
void mm_av(const __half* __restrict__ Eh, float* __restrict__ Aout,
           float* __restrict__ Cout)
{
    MM_PROLOGUE();
    const int b = blockIdx.z;
    const int n0 = blockIdx.x * 128, m0 = blockIdx.y * 128;

    const __half* pE  = Eh + (size_t)b * LL * LL + (size_t)m0 * LL;
    float*        pA  = Aout + (size_t)b * LL * LL + (size_t)m0 * LL;
    const __half* pBh = g_VTh + (size_t)b * DD * LL + (size_t)n0 * LL;

    const int NCH = LL / 32;   // 64
    const int wlo = blockIdx.x * 32, whi = wlo + 32;

    uint2 e2[4];
#pragma unroll
    for (int t = 0; t < 4; t++) {
        const int q = tid + t * 256;
        const int row = q >> 3, seg = q & 7;
        e2[t] = *reinterpret_cast<const uint2*>(pE + (size_t)row * LL + seg * 4);
    }
    CPSTAGE1(BA_B(0), pBh, LL, 0);
    CP_COMMIT();
    CPSTAGE1(BA_B(1), pBh, LL, 1);
    CP_COMMIT();

    // transform chunk 0 into A buf 0; prefetch E chunk 1
    {
        const bool wA = (0 >= wlo) && (0 < whi);
#pragma unroll
        for (int t = 0; t < 4; t++) {
            const int q = tid + t * 256;
            const int row = q >> 3, seg = q & 7;
            const int k = seg * 4;
            float2 f0 = __half22float2(*reinterpret_cast<__half2*>(&e2[t].x));
            float2 f1 = __half22float2(*reinterpret_cast<__half2*>(&e2[t].y));
            float4 m4 = *reinterpret_cast<const float4*>(&g_m[b][k]);
            float4 i4 = *reinterpret_cast<const float4*>(&g_is[b][k]);
            float v[4];
            v[0] = fexp(f0.x - m4.x) * i4.x;
            v[1] = fexp(f0.y - m4.y) * i4.y;
            v[2] = fexp(f1.x - m4.z) * i4.z;
            v[3] = fexp(f1.y - m4.w) * i4.w;
            if (wA)
                *reinterpret_cast<float4*>(pA + (size_t)row * LL + k) =
                    make_float4(v[0], v[1], v[2], v[3]);
            const uint32_t so = row * PITCH + seg * 8;
            *reinterpret_cast<uint2*>(smem + so) =
                make_uint2(h2pack(v[0], v[1]), h2pack(v[2], v[3]));
        }
#pragma unroll
        for (int t = 0; t < 4; t++) {
            const int q = tid + t * 256;
            const int row = q >> 3, seg = q & 7;
            e2[t] = *reinterpret_cast<const uint2*>(pE + (size_t)row * LL + 32 + seg * 4);
        }
    }

    int abuf = 0, bbuf = 0;
    for (int kc = 0; kc < NCH; kc++) {
        if (kc == NCH - 1) { CP_WAIT0(); } else { CP_WAIT1(); }
        __syncthreads();
        COMPUTE1(BA_A(abuf), BA_B(bbuf));
        if (kc + 1 < NCH) {
            const int c = kc + 1;
            const bool wA = (c >= wlo) && (c < whi);
            const int na = abuf ^ 1;
#pragma unroll
            for (int t = 0; t < 4; t++) {
                const int q = tid + t * 256;
                const int row = q >> 3, seg = q & 7;
                const int k = c * 32 + seg * 4;
                float2 f0 = __half22float2(*reinterpret_cast<__half2*>(&e2[t].x));
                float2 f1 = __half22float2(*reinterpret_cast<__half2*>(&e2[t].y));
                float4 m4 = *reinterpret_cast<const float4*>(&g_m[b][k]);
                float4 i4 = *reinterpret_cast<const float4*>(&g_is[b][k]);
                float v[4];
                v[0] = fexp(f0.x - m4.x) * i4.x;
                v[1] = fexp(f0.y - m4.y) * i4.y;
                v[2] = fexp(f1.x - m4.z) * i4.z;
                v[3] = fexp(f1.y - m4.w) * i4.w;
                if (wA)
                    *reinterpret_cast<float4*>(pA + (size_t)row * LL + k) =
                        make_float4(v[0], v[1], v[2], v[3]);
                const uint32_t so = row * PITCH + seg * 8;
                *reinterpret_cast<uint2*>(smem + na * TILEB + so) =
                    make_uint2(h2pack(v[0], v[1]), h2pack(v[2], v[3]));
            }
            if (c + 1 < NCH) {
#pragma unroll
                for (int t = 0; t < 4; t++) {
                    const int q = tid + t * 256;
                    const int row = q >> 3, seg = q & 7;
                    e2[t] = *reinterpret_cast<const uint2*>(
                        pE + (size_t)row * LL + (size_t)(c + 1) * 32 + seg * 4);
                }
            }
        }
        if (kc + 2 < NCH) {
            const int s = (bbuf + 2 >= 3) ? bbuf - 1 : bbuf + 2;
            CPSTAGE1(BA_B(s), pBh, LL, kc + 2);
            CP_COMMIT();
        }
        abuf ^= 1;
        bbuf = (bbuf + 1 == 3) ? 0 : bbuf + 1;
    }

    float* Cb = Cout + (size_t)b * 2 * LL * DD;
#pragma unroll
    for (int mt = 0; mt < 4; mt++) {
#pragma unroll
        for (int ni = 0; ni < 4; ni++) {
            const float* acc = d[mt * 4 + ni];
            const int row = m0 + wm * 64 + mt * 16 + (lane >> 2);
            const int col = n0 + wn * 32 + ni * 8 + (lane & 3) * 2;
            *reinterpret_cast<float2*>(&Cb[(size_t)row * DD + col]) =
                make_float2(acc[0], acc[1]);
            *reinterpret_cast<float2*>(&Cb[(size_t)(row + 8) * DD + col]) =
                make_float2(acc[2], acc[3]);
        }
    }
}

// ---------------------------------------------------------------------------
// QKV (fp16 1-term): {Q,K,V}[r,n] = x[r,:].W[n,:] + b[n]
// w==2 (V): transposed fp16 output written directly via smem transpose.
// ---------------------------------------------------------------------------
__global__ __launch_bounds__(256, 2)
void mm_qkv(const float* __restrict__ bq, const float* __restrict__ bk,
            const float* __restrict__ bv, float* __restrict__ Sp)
{
    MM_PROLOGUE();
    const int w = blockIdx.z;
    const int n0 = blockIdx.x * 128, m0 = blockIdx.y * 128;

    const __half* pAh = g_xf + (size_t)m0 * DD;
    const __half* pBh = g_Wf[w] + (size_t)n0 * DD;

    const int NCH = DD / 32;
    CPSTAGE1(BE_AH(0), pAh, DD, 0);
    CPSTAGE1(BE_BH(0), pBh, DD, 0);
    CP_COMMIT();
    CPSTAGE1(BE_AH(1), pAh, DD, 1);
    CPSTAGE1(BE_BH(1), pBh, DD, 1);
    CP_COMMIT();

    int bi = 0;
    for (int kc = 0; kc < NCH; kc++) {
        if (kc == NCH - 1) { CP_WAIT0(); } else { CP_WAIT1(); }
        __syncthreads();
        COMPUTE1(BE_AH(bi), BE_BH(bi));
        if (kc + 2 < NCH) {
            const int s = (bi + 2 >= 3) ? bi - 1 : bi + 2;
            CPSTAGE1(BE_AH(s), pAh, DD, kc + 2);
            CPSTAGE1(BE_BH(s), pBh, DD, kc + 2);
            CP_COMMIT();
        }
        bi = (bi + 1 == 3) ? 0 : bi + 1;
    }

    const float* bias = (w == 0) ? bq : (w == 1) ? bk : bv;
    const int b = m0 >> 11;            // batch (m-tiles never straddle batches)
    const int l0 = m0 & 2047;

    if (w < 2) {
#pragma unroll
        for (int mt = 0; mt < 4; mt++) {
#pragma unroll
            for (int ni = 0; ni < 4; ni++) {
                float* acc = d[mt * 4 + ni];
                const int row = m0 + wm * 64 + mt * 16 + (lane >> 2);
                const int col = n0 + wn * 32 + ni * 8 + (lane & 3) * 2;
                const float b0 = bias[col], b1 = bias[col + 1];
                float v0 = acc[0] + b0, v1 = acc[1] + b1;
                float v2 = acc[2] + b0, v3 = acc[3] + b1;
                const size_t o0 = (size_t)row * DD + col;
                const size_t o1 = (size_t)(row + 8) * DD + col;
                if (w == 0) {
                    const int li = row & 2047, li8 = (row + 8) & 2047;
                    float* q0 = Sp + (size_t)b * 2 * LL * DD + (size_t)li * DD + col;
                    float* q1 = Sp + (size_t)b * 2 * LL * DD + (size_t)li8 * DD + col;
                    *reinterpret_cast<float2*>(q0) = make_float2(v0, v1);
                    *reinterpret_cast<float2*>(q1) = make_float2(v2, v3);
                    *reinterpret_cast<uint32_t*>(&g_Qh[o0]) = h2pack(v0, v1);
                    *reinterpret_cast<uint32_t*>(&g_Qh[o1]) = h2pack(v2, v3);
                } else {
                    *reinterpret_cast<uint32_t*>(&g_Kh[o0]) = h2pack(v0, v1);
                    *reinterpret_cast<uint32_t*>(&g_Kh[o1]) = h2pack(v2, v3);
                }
            }
        }
    } else {
        // V: transpose 128(l) x 128(d) tile in smem -> g_VTh[b][d][l] fp16
        __syncthreads();
        __half* sT = reinterpret_cast<__half*>(smem);  // [128 d][pitch 136]
#pragma unroll
        for (int mt = 0; mt < 4; mt++) {
#pragma unroll
            for (int ni = 0; ni < 4; ni++) {
                const float* acc = d[mt * 4 + ni];
                const int lr = wm * 64 + mt * 16 + (lane >> 2);       // local l
                const int dc = wn * 32 + ni * 8 + (lane & 3) * 2;     // local d
                const float b0 = bias[n0 + dc], b1 = bias[n0 + dc + 1];
                sT[(dc    ) * 136 + lr    ] = __float2half(acc[0] + b0);
                sT[(dc + 1) * 136 + lr    ] = __float2half(acc[1] + b1);
                sT[(dc    ) * 136 + lr + 8] = __float2half(acc[2] + b0);
                sT[(dc + 1) * 136 + lr + 8] = __float2half(acc[3] + b1);
            }
        }
        __syncthreads();
        __half* Tb = g_VTh + (size_t)b * DD * LL;
#pragma unroll
        for (int t = 0; t < 8; t++) {
            const int i = tid + t * 256;       // 0..2047
            const int dr = i >> 4, seg = i & 15;
            *reinterpret_cast<uint4*>(&Tb[(size_t)(n0 + dr) * LL + l0 + seg * 8]) =
                *reinterpret_cast<const uint4*>(&sT[dr * 136 + seg * 8]);
        }
    }
}

// ---------------------------------------------------------------------------
// Softmax combine (16 partials per column)
// ---------------------------------------------------------------------------
__global__ __launch_bounds__(256)
void softmax_combine()
{
    const int b = blockIdx.y;
    const int col = blockIdx.x * 256 + threadIdx.x;
    float m = -1e30f;
#pragma unroll
    for (int c = 0; c < 16; c++) m = fmaxf(m, g_pm[b][c][col]);
    float s = 0.f;
#pragma unroll
    for (int c = 0; c < 16; c++) s += g_ps[b][c][col] * fexp(g_pm[b][c][col] - m);
    g_m[b][col] = m;
    g_is[b][col] = 1.0f / s;
}

// ---------------------------------------------------------------------------
// Launch
// ---------------------------------------------------------------------------
extern "C" void kernel_launch(void* const* d_in, const int* in_sizes, int n_in,
                              void* d_out, int out_size)
{
    const float* x  = (const float*)d_in[0];
    const float* Wq = (const float*)d_in[1];
    const float* bq = (const float*)d_in[2];
    const float* Wk = (const float*)d_in[3];
    const float* bk = (const float*)d_in[4];
    const float* Wv = (const float*)d_in[5];
    const float* bv = (const float*)d_in[6];

    float* out  = (float*)d_out;
    float* Sp   = out;                                  // [B, 2L, D]
    float* Aout = out + (size_t)BB * 2 * LL * DD;       // [B, L, L]

    __half *gE;
    cudaGetSymbolAddress((void**)&gE, g_E);

    cudaFuncSetAttribute(mm_e,   cudaFuncAttributeMaxDynamicSharedMemorySize, SMEM_E);
    cudaFuncSetAttribute(mm_av,  cudaFuncAttributeMaxDynamicSharedMemorySize, SMEM_AV);
    cudaFuncSetAttribute(mm_qkv, cudaFuncAttributeMaxDynamicSharedMemorySize, SMEM_E);

    // 1) convert x and W to fp16
    const size_t nx = (size_t)BB * LL * DD;
    cvtx_kernel<<<(unsigned)(nx / 1024), 256>>>(x);
    cvtw_kernel<<<dim3(DD * DD / 1024, 3), 256>>>(Wq, Wk, Wv);

    // 2) QKV on tensor cores (fp16 1-term); V written transposed fp16
    mm_qkv<<<dim3(2, (BB * LL) / 128, 3), 256, SMEM_E>>>(bq, bk, bv, Sp);

    // 3) E = Q K^T / 16 (fp16 1-term), E stored fp16, fused softmax partials
    mm_e<<<dim3(LL / 128, LL / 128, BB), 256, SMEM_E>>>(gE);

    // 4) softmax finalize
    softmax_combine<<<dim3(LL / 256, BB), 256>>>();

    // 5) C = A V (fp16 1-term; A from fp16 E on the fly; n-tiles split A writes)
    mm_av<<<dim3(DD / 128, LL / 128, BB), 256, SMEM_AV>>>(gE, Aout, Sp + (size_t)LL * DD);

    (void)in_sizes; (void)n_in; (void)out_size;
}

// round 17
// speedup vs baseline: 1.1326x; 1.0096x over previous
#include <cuda_runtime.h>
#include <cuda_bf16.h>
#include <cuda_fp16.h>
#include <cstdint>
#include <cstddef>

// Problem constants
#define BB 8
#define LL 2048
#define DD 256

// ---------------------------------------------------------------------------
// Scratch (__device__ globals; no allocation allowed)
// ---------------------------------------------------------------------------
__device__ __half         g_E [(size_t)BB * LL * LL];      // E fp16 (67 MB)
__device__ __half         g_xf[(size_t)BB * LL * DD];      // x fp16
__device__ __half         g_Wf[3][DD * DD];                // Wq,Wk,Wv fp16
__device__ __half         g_Qh[(size_t)BB * LL * DD];
__device__ __half         g_Kh[(size_t)BB * LL * DD];
__device__ __half         g_VTh[(size_t)BB * DD * LL];     // V^T fp16 [b][d][l]
__device__ float g_pm[BB][16][LL];
__device__ float g_ps[BB][16][LL];
__device__ float g_m [BB][LL];
__device__ float g_is[BB][LL];

// ---------------------------------------------------------------------------
// Helpers
// ---------------------------------------------------------------------------
__device__ __forceinline__ uint32_t smem_u32(const void* p) {
    uint32_t a;
    asm("{ .reg .u64 t; cvta.to.shared.u64 t, %1; cvt.u32.u64 %0, t; }"
        : "=r"(a) : "l"(p));
    return a;
}

#define LDSM4(r, addr)                                                        \
    asm volatile("ldmatrix.sync.aligned.m8n8.x4.shared.b16 {%0,%1,%2,%3}, [%4];" \
                 : "=r"((r)[0]), "=r"((r)[1]), "=r"((r)[2]), "=r"((r)[3])     \
                 : "r"(addr))

#define MMA_F16(d, a, b0, b1)                                                 \
    asm volatile("mma.sync.aligned.m16n8k16.row.col.f32.f16.f16.f32 "         \
                 "{%0,%1,%2,%3}, {%4,%5,%6,%7}, {%8,%9}, {%0,%1,%2,%3};"      \
                 : "+f"((d)[0]), "+f"((d)[1]), "+f"((d)[2]), "+f"((d)[3])     \
                 : "r"((a)[0]), "r"((a)[1]), "r"((a)[2]), "r"((a)[3]),        \
                   "r"(b0), "r"(b1))

#define CP16(dst, src)                                                        \
    asm volatile("cp.async.cg.shared.global [%0], [%1], 16;"                  \
                 :: "r"(dst), "l"(src))
#define CP_COMMIT() asm volatile("cp.async.commit_group;" ::: "memory")
#define CP_WAIT1()  asm volatile("cp.async.wait_group 1;" ::: "memory")
#define CP_WAIT0()  asm volatile("cp.async.wait_group 0;" ::: "memory")

// Fast exp on the fma pipe (no MUFU); rel err ~2.4e-6
__device__ __forceinline__ float fexp(float x)
{
    x = fmaxf(x, -87.0f);
    float y = x * 1.4426950408889634f;
    float t = y + 12582912.0f;
    int   i = __float_as_int(t) - 0x4B400000;
    float f = y - (t - 12582912.0f);
    float p = 1.3333558146e-3f;
    p = fmaf(p, f, 9.6181291076e-3f);
    p = fmaf(p, f, 5.5504108664e-2f);
    p = fmaf(p, f, 2.4022650696e-1f);
    p = fmaf(p, f, 6.9314718056e-1f);
    p = fmaf(p, f, 1.0f);
    return __int_as_float(__float_as_int(p) + (i << 23));
}

__device__ __forceinline__ uint32_t h2pack(float a, float b)
{
    __half2 hh = __floats2half2_rn(a, b);
    return *reinterpret_cast<uint32_t*>(&hh);
}

// ---------------------------------------------------------------------------
// x: fp32 -> fp16
// ---------------------------------------------------------------------------
__global__ __launch_bounds__(256)
void cvtx_kernel(const float* __restrict__ src)
{
    const size_t i = ((size_t)blockIdx.x * 256 + threadIdx.x) * 4;
    float4 v4 = *reinterpret_cast<const float4*>(src + i);
    *reinterpret_cast<uint2*>(&g_xf[i]) = make_uint2(
        h2pack(v4.x, v4.y), h2pack(v4.z, v4.w));
}

// W: fp32 -> fp16 (blockIdx.y selects Wq/Wk/Wv)
__global__ __launch_bounds__(256)
void cvtw_kernel(const float* __restrict__ Wq, const float* __restrict__ Wk,
                 const float* __restrict__ Wv)
{
    const int w = blockIdx.y;
    const float* src = (w == 0) ? Wq : (w == 1) ? Wk : Wv;
    const size_t i = ((size_t)blockIdx.x * 256 + threadIdx.x) * 4;
    float4 v4 = *reinterpret_cast<const float4*>(src + i);
    *reinterpret_cast<uint2*>(&g_Wf[w][i]) = make_uint2(
        h2pack(v4.x, v4.y), h2pack(v4.z, v4.w));
}

// ---------------------------------------------------------------------------
// MMA kernels: CTA tile 128x128, 256 threads (8 warps 64x32).
// mm_e/mm_qkv: BK=64 chunks, PITCH2=144 rows, 3-stage / 1 barrier per chunk.
// mm_av: BK=32, PITCH=80 (unchanged R14/R16 structure).
// ---------------------------------------------------------------------------
#define PITCH  80
#define PITCH2 144
#define TILEB   (128 * PITCH)          // 10240
#define TILE64  (128 * PITCH2)         // 18432
#define BUFE    (2 * TILE64)           // stage: Ah|Bh (BK=64)
#define SMEM_E  (3 * BUFE)             // 110592
#define SMEM_AV (5 * TILEB)            // 51200: A x2 | B x3

// stage 128 rows x 32 halves (BK=32, pitch 80)
#define CPSTAGE1(dh, srch, ld, kc)                                            \
    _Pragma("unroll")                                                         \
    for (int t = 0; t < 2; t++) {                                             \
        const int q = tid + t * 256;                                          \
        const int row = q >> 2, seg = q & 3;                                  \
        const uint32_t so = row * PITCH + seg * 16;                           \
        const size_t go = (size_t)row * (ld) + (size_t)(kc) * 32 + seg * 8;   \
        CP16((dh) + so, (srch) + go);                                         \
    }

// stage 128 rows x 64 halves (BK=64, pitch 144)
#define CPSTAGE64(dh, srch, ld, kc)                                           \
    _Pragma("unroll")                                                         \
    for (int t = 0; t < 4; t++) {                                             \
        const int q = tid + t * 256;                                          \
        const int row = q >> 3, seg = q & 7;                                  \
        const uint32_t so = row * PITCH2 + seg * 16;                          \
        const size_t go = (size_t)row * (ld) + (size_t)(kc) * 64 + seg * 8;   \
        CP16((dh) + so, (srch) + go);                                         \
    }

// 1-term fp16, parametric pitch/kk-count: D += Ah*Bh
#define COMPUTE1P(aH, bH, P, KKN)                                             \
    _Pragma("unroll")                                                         \
    for (int kk = 0; kk < (KKN); kk++) {                                      \
        uint32_t bhf[2][4];                                                   \
        LDSM4(bhf[0], (bH) + relB + kk * 32);                                 \
        LDSM4(bhf[1], (bH) + relB + 16 * (P) + kk * 32);                      \
        _Pragma("unroll")                                                     \
        for (int mt = 0; mt < 4; mt++) {                                      \
            uint32_t ah[4];                                                   \
            LDSM4(ah, (aH) + relA + mt * 16 * (P) + kk * 32);                 \
            _Pragma("unroll")                                                 \
            for (int g = 0; g < 2; g++) {                                     \
                _Pragma("unroll")                                             \
                for (int h = 0; h < 2; h++) {                                 \
                    float* acc = d[mt * 4 + g * 2 + h];                       \
                    MMA_F16(acc, ah, bhf[g][h], bhf[g][h + 2]);               \
                }                                                             \
            }                                                                 \
        }                                                                     \
    }

#define MM_PROLOGUE_P(P)                                                      \
    extern __shared__ __align__(16) uint8_t smem[];                           \
    const uint32_t sb = smem_u32(smem);                                       \
    const int tid = threadIdx.x;                                              \
    const int lane = tid & 31;                                                \
    const int wm = (tid >> 5) & 1;                                            \
    const int wn = tid >> 6;                                                  \
    const uint32_t lrow = lane & 15, lhalf = lane >> 4;                       \
    const uint32_t relA = (wm * 64 + lrow) * (P) + lhalf * 16;                \
    const uint32_t relB = (wn * 32 + lrow) * (P) + lhalf * 16;                \
    float d[16][4];                                                           \
    _Pragma("unroll")                                                         \
    for (int i = 0; i < 16; i++)                                              \
        _Pragma("unroll")                                                     \
        for (int j = 0; j < 4; j++) d[i][j] = 0.0f;

// BK=64 3-stage buffers (mm_e, mm_qkv)
#define BE_AH(s) (sb + (s) * BUFE)
#define BE_BH(s) (sb + (s) * BUFE + TILE64)
// mm_av: A x2, B x3 (BK=32)
#define BA_A(s)  (sb + (s) * TILEB)
#define BA_B(s)  (sb + (2 + (s)) * TILEB)

// BK=64 3-stage mainloop over NCH=4 chunks, one barrier per chunk
#define MAINLOOP64(pAh, pBh, ld)                                              \
    CPSTAGE64(BE_AH(0), pAh, ld, 0);                                          \
    CPSTAGE64(BE_BH(0), pBh, ld, 0);                                          \
    CP_COMMIT();                                                              \
    CPSTAGE64(BE_AH(1), pAh, ld, 1);                                          \
    CPSTAGE64(BE_BH(1), pBh, ld, 1);                                          \
    CP_COMMIT();                                                              \
    {                                                                         \
        int bi = 0;                                                           \
        for (int kc = 0; kc < 4; kc++) {                                      \
            if (kc == 3) { CP_WAIT0(); } else { CP_WAIT1(); }                 \
            __syncthreads();                                                  \
            COMPUTE1P(BE_AH(bi), BE_BH(bi), PITCH2, 4);                       \
            if (kc + 2 < 4) {                                                 \
                const int s = (bi + 2 >= 3) ? bi - 1 : bi + 2;                \
                CPSTAGE64(BE_AH(s), pAh, ld, kc + 2);                         \
                CPSTAGE64(BE_BH(s), pBh, ld, kc + 2);                         \
                CP_COMMIT();                                                  \
            }                                                                 \
            bi = (bi + 1 == 3) ? 0 : bi + 1;                                  \
        }                                                                     \
    }

// ---------------------------------------------------------------------------
// E = Q K^T / 16 (fp16 1-term, BK=64), E fp16, fused softmax partials.
// ---------------------------------------------------------------------------
__global__ __launch_bounds__(256, 2)
void mm_e(__half* __restrict__ Eh)
{
    MM_PROLOGUE_P(PITCH2);
    const int b = blockIdx.z;
    const int n0 = blockIdx.x * 128, m0 = blockIdx.y * 128;

    const __half* pAh = g_Qh + (size_t)b * LL * DD + (size_t)m0 * DD;
    const __half* pBh = g_Kh + (size_t)b * LL * DD + (size_t)n0 * DD;

    MAINLOOP64(pAh, pBh, DD);

#pragma unroll
    for (int i = 0; i < 16; i++)
#pragma unroll
        for (int j = 0; j < 4; j++) d[i][j] *= (1.0f / 16.0f);

    __half* Cb = Eh + (size_t)b * LL * LL;
#pragma unroll
    for (int mt = 0; mt < 4; mt++) {
#pragma unroll
        for (int ni = 0; ni < 4; ni++) {
            const float* acc = d[mt * 4 + ni];
            const int row = m0 + wm * 64 + mt * 16 + (lane >> 2);
            const int col = n0 + wn * 32 + ni * 8 + (lane & 3) * 2;
            *reinterpret_cast<uint32_t*>(&Cb[(size_t)row * LL + col]) =
                h2pack(acc[0], acc[1]);
            *reinterpret_cast<uint32_t*>(&Cb[(size_t)(row + 8) * LL + col]) =
                h2pack(acc[2], acc[3]);
        }
    }

    float* sMx = reinterpret_cast<float*>(smem);
    float* sSm = reinterpret_cast<float*>(smem) + 256;
    __syncthreads();
#pragma unroll
    for (int ni = 0; ni < 4; ni++) {
#pragma unroll
        for (int p = 0; p < 2; p++) {
            float mx = -1e30f;
#pragma unroll
            for (int mt = 0; mt < 4; mt++)
                mx = fmaxf(mx, fmaxf(d[mt * 4 + ni][p], d[mt * 4 + ni][p + 2]));
#pragma unroll
            for (int off = 4; off < 32; off <<= 1)
                mx = fmaxf(mx, __shfl_xor_sync(0xFFFFFFFFu, mx, off));
            float sm = 0.0f;
#pragma unroll
            for (int mt = 0; mt < 4; mt++)
                sm += fexp(d[mt * 4 + ni][p] - mx) + fexp(d[mt * 4 + ni][p + 2] - mx);
#pragma unroll
            for (int off = 4; off < 32; off <<= 1)
                sm += __shfl_xor_sync(0xFFFFFFFFu, sm, off);
            if ((lane >> 2) == 0) {
                const int c = wn * 32 + ni * 8 + (lane & 3) * 2 + p;
                sMx[wm * 128 + c] = mx;
                sSm[wm * 128 + c] = sm;
            }
        }
    }
    __syncthreads();
    if (tid < 128) {
        float m0v = sMx[tid], m1v = sMx[128 + tid];
        float nm = fmaxf(m0v, m1v);
        float s = sSm[tid] * fexp(m0v - nm) + sSm[128 + tid] * fexp(m1v - nm);
        g_pm[b][blockIdx.y][n0 + tid] = nm;
        g_is[b][0] = g_is[b][0];   // no-op keep
        g_ps[b][blockIdx.y][n0 + tid] = s;
    }
}

// ---------------------------------------------------------------------------
// C = A V^T (fp16 1-term), BK=32, 3-stage B / 2-stage A, 1 barrier per chunk.
// (R14/R16 structure, unchanged)
// ---------------------------------------------------------------------------
__global__ __launch_bounds__(256, 2)
void mm_av(const __half* __restrict__ Eh, float* __restrict__ Aout,
           float* __restrict__ Cout)
{
    MM_PROLOGUE_P(PITCH);
    const int b = blockIdx.z;
    const int n0 = blockIdx.x * 128, m0 = blockIdx.y * 128;

    const __half* pE  = Eh + (size_t)b * LL * LL + (size_t)m0 * LL;
    float*        pA  = Aout + (size_t)b * LL * LL + (size_t)m0 * LL;
    const __half* pBh = g_VTh + (size_t)b * DD * LL + (size_t)n0 * LL;

    const int NCH = LL / 32;   // 64
    const int wlo = blockIdx.x * 32, whi = wlo + 32;

    uint2 e2[4];
#pragma unroll
    for (int t = 0; t < 4; t++) {
        const int q = tid + t * 256;
        const int row = q >> 3, seg = q & 7;
        e2[t] = *reinterpret_cast<const uint2*>(pE + (size_t)row * LL + seg * 4);
    }
    CPSTAGE1(BA_B(0), pBh, LL, 0);
    CP_COMMIT();
    CPSTAGE1(BA_B(1), pBh, LL, 1);
    CP_COMMIT();

    {
        const bool wA = (0 >= wlo) && (0 < whi);
#pragma unroll
        for (int t = 0; t < 4; t++) {
            const int q = tid + t * 256;
            const int row = q >> 3, seg = q & 7;
            const int k = seg * 4;
            float2 f0 = __half22float2(*reinterpret_cast<__half2*>(&e2[t].x));
            float2 f1 = __half22float2(*reinterpret_cast<__half2*>(&e2[t].y));
            float4 m4 = *reinterpret_cast<const float4*>(&g_m[b][k]);
            float4 i4 = *reinterpret_cast<const float4*>(&g_is[b][k]);
            float v[4];
            v[0] = fexp(f0.x - m4.x) * i4.x;
            v[1] = fexp(f0.y - m4.y) * i4.y;
            v[2] = fexp(f1.x - m4.z) * i4.z;
            v[3] = fexp(f1.y - m4.w) * i4.w;
            if (wA)
                *reinterpret_cast<float4*>(pA + (size_t)row * LL + k) =
                    make_float4(v[0], v[1], v[2], v[3]);
            const uint32_t so = row * PITCH + seg * 8;
            *reinterpret_cast<uint2*>(smem + so) =
                make_uint2(h2pack(v[0], v[1]), h2pack(v[2], v[3]));
        }
#pragma unroll
        for (int t = 0; t < 4; t++) {
            const int q = tid + t * 256;
            const int row = q >> 3, seg = q & 7;
            e2[t] = *reinterpret_cast<const uint2*>(pE + (size_t)row * LL + 32 + seg * 4);
        }
    }

    int abuf = 0, bbuf = 0;
    for (int kc = 0; kc < NCH; kc++) {
        if (kc == NCH - 1) { CP_WAIT0(); } else { CP_WAIT1(); }
        __syncthreads();
        COMPUTE1P(BA_A(abuf), BA_B(bbuf), PITCH, 2);
        if (kc + 1 < NCH) {
            const int c = kc + 1;
            const bool wA = (c >= wlo) && (c < whi);
            const int na = abuf ^ 1;
#pragma unroll
            for (int t = 0; t < 4; t++) {
                const int q = tid + t * 256;
                const int row = q >> 3, seg = q & 7;
                const int k = c * 32 + seg * 4;
                float2 f0 = __half22float2(*reinterpret_cast<__half2*>(&e2[t].x));
                float2 f1 = __half22float2(*reinterpret_cast<__half2*>(&e2[t].y));
                float4 m4 = *reinterpret_cast<const float4*>(&g_m[b][k]);
                float4 i4 = *reinterpret_cast<const float4*>(&g_is[b][k]);
                float v[4];
                v[0] = fexp(f0.x - m4.x) * i4.x;
                v[1] = fexp(f0.y - m4.y) * i4.y;
                v[2] = fexp(f1.x - m4.z) * i4.z;
                v[3] = fexp(f1.y - m4.w) * i4.w;
                if (wA)
                    *reinterpret_cast<float4*>(pA + (size_t)row * LL + k) =
                        make_float4(v[0], v[1], v[2], v[3]);
                const uint32_t so = row * PITCH + seg * 8;
                *reinterpret_cast<uint2*>(smem + na * TILEB + so) =
                    make_uint2(h2pack(v[0], v[1]), h2pack(v[2], v[3]));
            }
            if (c + 1 < NCH) {
#pragma unroll
                for (int t = 0; t < 4; t++) {
                    const int q = tid + t * 256;
                    const int row = q >> 3, seg = q & 7;
                    e2[t] = *reinterpret_cast<const uint2*>(
                        pE + (size_t)row * LL + (size_t)(c + 1) * 32 + seg * 4);
                }
            }
        }
        if (kc + 2 < NCH) {
            const int s = (bbuf + 2 >= 3) ? bbuf - 1 : bbuf + 2;
            CPSTAGE1(BA_B(s), pBh, LL, kc + 2);
            CP_COMMIT();
        }
        abuf ^= 1;
        bbuf = (bbuf + 1 == 3) ? 0 : bbuf + 1;
    }

    float* Cb = Cout + (size_t)b * 2 * LL * DD;
#pragma unroll
    for (int mt = 0; mt < 4; mt++) {
#pragma unroll
        for (int ni = 0; ni < 4; ni++) {
            const float* acc = d[mt * 4 + ni];
            const int row = m0 + wm * 64 + mt * 16 + (lane >> 2);
            const int col = n0 + wn * 32 + ni * 8 + (lane & 3) * 2;
            *reinterpret_cast<float2*>(&Cb[(size_t)row * DD + col]) =
                make_float2(acc[0], acc[1]);
            *reinterpret_cast<float2*>(&Cb[(size_t)(row + 8) * DD + col]) =
                make_float2(acc[2], acc[3]);
        }
    }
}

// ---------------------------------------------------------------------------
// QKV (fp16 1-term, BK=64): {Q,K,V}[r,n] = x[r,:].W[n,:] + b[n]
// w==2 (V): transposed fp16 output via smem transpose.
// ---------------------------------------------------------------------------
__global__ __launch_bounds__(256, 2)
void mm_qkv(const float* __restrict__ bq, const float* __restrict__ bk,
            const float* __restrict__ bv, float* __restrict__ Sp)
{
    MM_PROLOGUE_P(PITCH2);
    const int w = blockIdx.z;
    const int n0 = blockIdx.x * 128, m0 = blockIdx.y * 128;

    const __half* pAh = g_xf + (size_t)m0 * DD;
    const __half* pBh = g_Wf[w] + (size_t)n0 * DD;

    MAINLOOP64(pAh, pBh, DD);

    const float* bias = (w == 0) ? bq : (w == 1) ? bk : bv;
    const int b = m0 >> 11;
    const int l0 = m0 & 2047;

    if (w < 2) {
#pragma unroll
        for (int mt = 0; mt < 4; mt++) {
#pragma unroll
            for (int ni = 0; ni < 4; ni++) {
                float* acc = d[mt * 4 + ni];
                const int row = m0 + wm * 64 + mt * 16 + (lane >> 2);
                const int col = n0 + wn * 32 + ni * 8 + (lane & 3) * 2;
                const float b0 = bias[col], b1 = bias[col + 1];
                float v0 = acc[0] + b0, v1 = acc[1] + b1;
                float v2 = acc[2] + b0, v3 = acc[3] + b1;
                const size_t o0 = (size_t)row * DD + col;
                const size_t o1 = (size_t)(row + 8) * DD + col;
                if (w == 0) {
                    const int li = row & 2047, li8 = (row + 8) & 2047;
                    float* q0 = Sp + (size_t)b * 2 * LL * DD + (size_t)li * DD + col;
                    float* q1 = Sp + (size_t)b * 2 * LL * DD + (size_t)li8 * DD + col;
                    *reinterpret_cast<float2*>(q0) = make_float2(v0, v1);
                    *reinterpret_cast<float2*>(q1) = make_float2(v2, v3);
                    *reinterpret_cast<uint32_t*>(&g_Qh[o0]) = h2pack(v0, v1);
                    *reinterpret_cast<uint32_t*>(&g_Qh[o1]) = h2pack(v2, v3);
                } else {
                    *reinterpret_cast<uint32_t*>(&g_Kh[o0]) = h2pack(v0, v1);
                    *reinterpret_cast<uint32_t*>(&g_Kh[o1]) = h2pack(v2, v3);
                }
            }
        }
    } else {
        // V: transpose 128(l) x 128(d) tile in smem -> g_VTh[b][d][l] fp16
        __syncthreads();
        __half* sT = reinterpret_cast<__half*>(smem);  // [128 d][pitch 136]
#pragma unroll
        for (int mt = 0; mt < 4; mt++) {
#pragma unroll
            for (int ni = 0; ni < 4; ni++) {
                const float* acc = d[mt * 4 + ni];
                const int lr = wm * 64 + mt * 16 + (lane >> 2);
                const int dc = wn * 32 + ni * 8 + (lane & 3) * 2;
                const float b0 = bias[n0 + dc], b1 = bias[n0 + dc + 1];
                sT[(dc    ) * 136 + lr    ] = __float2half(acc[0] + b0);
                sT[(dc + 1) * 136 + lr    ] = __float2half(acc[1] + b1);
                sT[(dc    ) * 136 + lr + 8] = __float2half(acc[2] + b0);
                sT[(dc + 1) * 136 + lr + 8] = __float2half(acc[3] + b1);
            }
        }
        __syncthreads();
        __half* Tb = g_VTh + (size_t)b * DD * LL;
#pragma unroll
        for (int t = 0; t < 8; t++) {
            const int i = tid + t * 256;
            const int dr = i >> 4, seg = i & 15;
            *reinterpret_cast<uint4*>(&Tb[(size_t)(n0 + dr) * LL + l0 + seg * 8]) =
                *reinterpret_cast<const uint4*>(&sT[dr * 136 + seg * 8]);
        }
    }
}

// ---------------------------------------------------------------------------
// Softmax combine (16 partials per column)
// ---------------------------------------------------------------------------
__global__ __launch_bounds__(256)
void softmax_combine()
{
    const int b = blockIdx.y;
    const int col = blockIdx.x * 256 + threadIdx.x;
    float m = -1e30f;
#pragma unroll
    for (int c = 0; c < 16; c++) m = fmaxf(m, g_pm[b][c][col]);
    float s = 0.f;
#pragma unroll
    for (int c = 0; c < 16; c++) s += g_ps[b][c][col] * fexp(g_pm[b][c][col] - m);
    g_m[b][col] = m;
    g_is[b][col] = 1.0f / s;
}

// ---------------------------------------------------------------------------
// Launch
// ---------------------------------------------------------------------------
extern "C" void kernel_launch(void* const* d_in, const int* in_sizes, int n_in,
                              void* d_out, int out_size)
{
    const float* x  = (const float*)d_in[0];
    const float* Wq = (const float*)d_in[1];
    const float* bq = (const float*)d_in[2];
    const float* Wk = (const float*)d_in[3];
    const float* bk = (const float*)d_in[4];
    const float* Wv = (const float*)d_in[5];
    const float* bv = (const float*)d_in[6];

    float* out  = (float*)d_out;
    float* Sp   = out;                                  // [B, 2L, D]
    float* Aout = out + (size_t)BB * 2 * LL * DD;       // [B, L, L]

    __half *gE;
    cudaGetSymbolAddress((void**)&gE, g_E);

    cudaFuncSetAttribute(mm_e,   cudaFuncAttributeMaxDynamicSharedMemorySize, SMEM_E);
    cudaFuncSetAttribute(mm_av,  cudaFuncAttributeMaxDynamicSharedMemorySize, SMEM_AV);
    cudaFuncSetAttribute(mm_qkv, cudaFuncAttributeMaxDynamicSharedMemorySize, SMEM_E);

    // 1) convert x and W to fp16
    const size_t nx = (size_t)BB * LL * DD;
    cvtx_kernel<<<(unsigned)(nx / 1024), 256>>>(x);
    cvtw_kernel<<<dim3(DD * DD / 1024, 3), 256>>>(Wq, Wk, Wv);

    // 2) QKV on tensor cores (fp16 1-term, BK=64); V written transposed fp16
    mm_qkv<<<dim3(2, (BB * LL) / 128, 3), 256, SMEM_E>>>(bq, bk, bv, Sp);

    // 3) E = Q K^T / 16 (fp16 1-term, BK=64), E fp16, fused softmax partials
    mm_e<<<dim3(LL / 128, LL / 128, BB), 256, SMEM_E>>>(gE);

    // 4) softmax finalize
    softmax_combine<<<dim3(LL / 256, BB), 256>>>();

    // 5) C = A V (fp16 1-term; A from fp16 E on the fly; n-tiles split A writes)
    mm_av<<<dim3(DD / 128, LL / 128, BB), 256, SMEM_AV>>>(gE, Aout, Sp + (size_t)LL * DD);

    (void)in_sizes; (void)n_in; (void)out_size;
}